// round 10
// baseline (speedup 1.0000x reference)
#include <cuda_runtime.h>

// y[o*48+p, n, m] = sum_i W0[p,i] * t4[o, (n-1)%56, m, i]
// t4[o, n', m, i] = sum_{j,k} xpad[o, j, n', m+k] * W1[j,k,i]  (pad 3 each side, width)
//
// 112 CTAs (one per (o, out-row n)), 512 threads. R5 skeleton.
// Stage 2 uses packed fma.rn.f32x2 (FFMA2): lane.x = output m0, lane.y = output m0+1.
// W1 stored pair-duplicated (w,w) in shared -> weight operand is one LDS.64.
// xs stores xpad[q] at word q (parity-preserving) -> even-k x-pairs are aligned LDS.64.

#define NCH 12
#define WID 56
#define XS 64               // xs row stride; xpad[q] at xs[j*64+q], q in [0,62); zeros at [0,3)+[59,62)
#define KS 7
#define NI 9
#define NP 48
#define W1DS 18             // w1d row stride in floats: [jk][2*i], dup pairs
#define THREADS 512

__device__ __forceinline__ float2 ffma2(float2 a, float2 b, float2 c) {
    unsigned long long au = *reinterpret_cast<unsigned long long*>(&a);
    unsigned long long bu = *reinterpret_cast<unsigned long long*>(&b);
    unsigned long long cu = *reinterpret_cast<unsigned long long*>(&c);
    unsigned long long du;
    asm("fma.rn.f32x2 %0, %1, %2, %3;" : "=l"(du) : "l"(au), "l"(bu), "l"(cu));
    return *reinterpret_cast<float2*>(&du);
}

__global__ __launch_bounds__(THREADS, 1)
void fused_sepconv_kernel(const float* __restrict__ x,
                          const float* __restrict__ W0,
                          const float* __restrict__ W1,
                          float* __restrict__ out) {
    __shared__ alignas(16) float xs[NCH * XS];          // 768
    __shared__ alignas(16) float w1d[NCH * KS * W1DS];  // 1512 (dup pairs)
    __shared__ alignas(16) float w0s[NP * NI];          // 432
    __shared__ float t4s[WID * NI];                     // 504, [m][i], stride 9

    const int b = blockIdx.x;             // 0..111
    const int o = b / WID;
    const int n = b % WID;
    const int nin = (n + WID - 1) % WID;  // roll(+1) along height
    const int t = threadIdx.x;

    // ---- Phase 1: all global loads issued first (max MLP) ----
    float4 v = make_float4(0.f, 0.f, 0.f, 0.f);
    float w0v = 0.f, w0v2 = 0.f, w0v3 = 0.f;
    if (t < 168) {
        int j  = t / 14;
        int q4 = t % 14;
        v = *(const float4*)&x[(((o * NCH + j) * WID + nin) * WID) + 4 * q4];
    } else if (t < 357) {
        v = *(const float4*)&W1[4 * (t - 168)];
    } else if (t < 501) {
        w0v  = W0[t - 357];
        w0v2 = W0[t - 357 + 144];
        w0v3 = W0[t - 357 + 288];
    }

    // Scatter to shared
    if (t < 168) {
        // x col c lives at xs[j*64 + 3 + c]  (xpad[q] == xs[q]); scalar STS keeps parity
        int j  = t / 14;
        int q4 = t % 14;
        float* dst = &xs[j * XS + 3 + 4 * q4];
        dst[0] = v.x; dst[1] = v.y; dst[2] = v.z; dst[3] = v.w;
        if (q4 == 0) {
            xs[j * XS + 0] = 0.f;
            xs[j * XS + 1] = 0.f;
            xs[j * XS + 2] = 0.f;
        } else if (q4 == 13) {
            xs[j * XS + 59] = 0.f;
            xs[j * XS + 60] = 0.f;
            xs[j * XS + 61] = 0.f;
        }
    } else if (t < 357) {
        // W1 element ee = jk*9 + i  ->  dup pair at w1d[jk*18 + 2*i]
        int e = 4 * (t - 168);
        const float* sv = (const float*)&v;
        #pragma unroll
        for (int r = 0; r < 4; ++r) {
            int ee = e + r;
            int jk = ee / NI;
            int i  = ee % NI;
            *(float2*)&w1d[jk * W1DS + 2 * i] = make_float2(sv[r], sv[r]);
        }
    } else if (t < 501) {
        w0s[t - 357]       = w0v;
        w0s[t - 357 + 144] = w0v2;
        w0s[t - 357 + 288] = w0v3;
    }

    __syncthreads();

    // ---- Stage 2: thread = (m-pair, i), i lane-fast; 252 threads; FFMA2 ----
    // acc.x accumulates output m0, acc.y output m0+1.
    if (t < 28 * NI) {
        const int i  = t % NI;
        const int m0 = 2 * (t / NI);

        float2 acc0 = make_float2(0.f, 0.f);
        float2 acc1 = make_float2(0.f, 0.f);

        #pragma unroll
        for (int j = 0; j < NCH; ++j) {
            const float2* xg = (const float2*)&xs[j * XS + m0];   // m0 even -> aligned
            float2 g0 = xg[0];   // (q m0,   m0+1)
            float2 g1 = xg[1];   // (q m0+2, m0+3)
            float2 g2 = xg[2];   // (q m0+4, m0+5)
            float2 g3 = xg[3];   // (q m0+6, m0+7)
            const float2* wd = (const float2*)&w1d[(j * KS) * W1DS + 2 * i];
            // row stride W1DS floats = 9 float2; wd[k*9] = dup weight for (j,k,i)

            acc0 = ffma2(g0,                         wd[0],  acc0);  // k=0
            acc1 = ffma2(make_float2(g0.y, g1.x),    wd[9],  acc1);  // k=1
            acc0 = ffma2(g1,                         wd[18], acc0);  // k=2
            acc1 = ffma2(make_float2(g1.y, g2.x),    wd[27], acc1);  // k=3
            acc0 = ffma2(g2,                         wd[36], acc0);  // k=4
            acc1 = ffma2(make_float2(g2.y, g3.x),    wd[45], acc1);  // k=5
            acc0 = ffma2(g3,                         wd[54], acc0);  // k=6
        }
        t4s[m0 * NI + i]       = acc0.x + acc1.x;
        t4s[(m0 + 1) * NI + i] = acc0.y + acc1.y;
    }

    __syncthreads();

    // ---- Stage 3: item = (mq, p); 672 items; R5-proven form ----
    for (int item = t; item < 14 * NP; item += THREADS) {
        const int mq = item / NP;         // warp-uniform-ish -> t4 reads broadcast
        const int p  = item % NP;         // stride-9 w0 reads, conflict-free
        const int m0 = 4 * mq;

        float w[NI];
        #pragma unroll
        for (int i = 0; i < NI; ++i) w[i] = w0s[p * NI + i];

        float4 r;
        float* rp = (float*)&r;
        #pragma unroll
        for (int mm = 0; mm < 4; ++mm) {
            const float* t4row = &t4s[(m0 + mm) * NI];
            float acc = 0.f;
            #pragma unroll
            for (int i = 0; i < NI; ++i) acc = fmaf(t4row[i], w[i], acc);
            rp[mm] = acc;
        }
        *(float4*)&out[(((o * NP + p) * WID + n) * WID) + m0] = r;
    }
}

extern "C" void kernel_launch(void* const* d_in, const int* in_sizes, int n_in,
                              void* d_out, int out_size) {
    // Bind inputs by size: x=75264, W0=432, W1=756
    const float* x  = (const float*)d_in[0];
    const float* W0 = (const float*)d_in[1];
    const float* W1 = (const float*)d_in[2];
    for (int i = 0; i < n_in; ++i) {
        if (in_sizes[i] == 75264) x  = (const float*)d_in[i];
        else if (in_sizes[i] == 432) W0 = (const float*)d_in[i];
        else if (in_sizes[i] == 756) W1 = (const float*)d_in[i];
    }
    float* out = (float*)d_out;

    fused_sepconv_kernel<<<2 * WID, THREADS>>>(x, W0, W1, out);
}

// round 11
// speedup vs baseline: 1.3527x; 1.3527x over previous
#include <cuda_runtime.h>

// y[o*48+p, n, m] = sum_i W0[p,i] * t4[o, (n-1)%56, m, i]
// t4[o, n', m, i] = sum_{j,k} xpad[o, j, n', m+k] * W1[j,k,i]  (pad 3 each side, width)
//
// 112 CTAs (one per (o, out-row n)), 224 threads = 7 warps.
// Warp w owns m in [8w, 8w+8): computes its t4 slice into a warp-private shared
// region, __syncwarp, then stage 3 for its own m's. ONE __syncthreads total.

#define NCH 12
#define WID 56
#define XS 64               // xs row stride; xpad[q] at xs[j*64+q]; zeros [0,3)+[59,62)
#define KS 7
#define NI 9
#define NP 48
#define T4W 80              // per-warp t4 region stride (floats): [i][8] padded
#define THREADS 224

__global__ __launch_bounds__(THREADS, 1)
void fused_sepconv_kernel(const float* __restrict__ x,
                          const float* __restrict__ W0,
                          const float* __restrict__ W1,
                          float* __restrict__ out) {
    __shared__ alignas(16) float xs[NCH * XS];        // 768
    __shared__ alignas(16) float w1s[NCH * KS * NI];  // 756
    __shared__ alignas(16) float w0s[NP * NI];        // 432
    __shared__ alignas(16) float t4s[7 * T4W];        // 560: warp-private [i][8] slices

    const int b = blockIdx.x;             // 0..111
    const int o = b / WID;
    const int n = b % WID;
    const int nin = (n + WID - 1) % WID;  // roll(+1) along height
    const int t = threadIdx.x;
    const int w = t >> 5;                 // warp 0..6
    const int l = t & 31;

    // ---- Phase 1: all global loads issued first (max MLP), then scatter ----
    float4 xv = make_float4(0.f, 0.f, 0.f, 0.f);
    float4 w1v = make_float4(0.f, 0.f, 0.f, 0.f);
    float w0a = 0.f, w0b = 0.f;
    if (t < 168) {
        int j  = t / 14;
        int q4 = t % 14;
        xv = *(const float4*)&x[(((o * NCH + j) * WID + nin) * WID) + 4 * q4];
    }
    if (t < 189) w1v = *(const float4*)&W1[4 * t];
    if (t < 216) { w0a = W0[t]; w0b = W0[t + 216]; }

    if (t < 168) {
        int j  = t / 14;
        int q4 = t % 14;
        // xpad[q] at xs[q]; x col c -> idx c+3 (scalar STS keeps parity mapping simple)
        float* dst = &xs[j * XS + 3 + 4 * q4];
        dst[0] = xv.x; dst[1] = xv.y; dst[2] = xv.z; dst[3] = xv.w;
        if (q4 == 0) {
            xs[j * XS + 0] = 0.f; xs[j * XS + 1] = 0.f; xs[j * XS + 2] = 0.f;
        } else if (q4 == 13) {
            xs[j * XS + 59] = 0.f; xs[j * XS + 60] = 0.f; xs[j * XS + 61] = 0.f;
        }
    }
    if (t < 189) *(float4*)&w1s[4 * t] = w1v;
    if (t < 216) { w0s[t] = w0a; w0s[t + 216] = w0b; }

    __syncthreads();   // the ONLY block barrier

    // ---- Stage 2 (warp-local): lanes 0..17 = (quad q, i); 4-m quad per lane ----
    if (l < 18) {
        const int q  = l / NI;            // 0,1
        const int i  = l % NI;            // lanes i-fast: w1 reads consecutive
        const int m0 = 8 * w + 4 * q;     // global m base of this quad

        float a0 = 0.f, a1 = 0.f, a2 = 0.f, a3 = 0.f;  // outputs m0..m0+3

        #pragma unroll
        for (int j = 0; j < NCH; ++j) {
            // window xpad[m0 .. m0+9] = 5 aligned float2
            const float2* xg = (const float2*)&xs[j * XS + m0];
            float2 g0 = xg[0], g1 = xg[1], g2 = xg[2], g3 = xg[3], g4 = xg[4];
            const float xw[10] = {g0.x, g0.y, g1.x, g1.y, g2.x,
                                  g2.y, g3.x, g3.y, g4.x, g4.y};
            const float* wj = &w1s[(j * KS) * NI + i];

            #pragma unroll
            for (int k = 0; k < KS; ++k) {
                const float wv = wj[k * NI];
                a0 = fmaf(xw[k],     wv, a0);
                a1 = fmaf(xw[k + 1], wv, a1);
                a2 = fmaf(xw[k + 2], wv, a2);
                a3 = fmaf(xw[k + 3], wv, a3);
            }
        }
        // warp-private region: [i][8], quad at offset 4q -> 16B-aligned float4 store
        *(float4*)&t4s[w * T4W + i * 8 + 4 * q] = make_float4(a0, a1, a2, a3);
    }

    __syncwarp();      // warp-local producer->consumer hand-off

    // ---- Stage 3 (warp-local): 96 float4 outputs per warp, 3 per lane ----
    #pragma unroll
    for (int r = 0; r < 3; ++r) {
        const int idx = r * 32 + l;       // 0..95
        const int p   = idx % NP;
        const int mq  = idx / NP;         // 0,1
        const int m0  = 8 * w + 4 * mq;

        const float* w0row = &w0s[p * NI];   // stride-9 scalar reads, conflict-free
        float4 res = make_float4(0.f, 0.f, 0.f, 0.f);
        float* rp = (float*)&res;
        #pragma unroll
        for (int i = 0; i < NI; ++i) {
            float4 tq = *(const float4*)&t4s[w * T4W + i * 8 + 4 * mq];  // broadcast
            const float wv = w0row[i];
            rp[0] = fmaf(tq.x, wv, rp[0]);
            rp[1] = fmaf(tq.y, wv, rp[1]);
            rp[2] = fmaf(tq.z, wv, rp[2]);
            rp[3] = fmaf(tq.w, wv, rp[3]);
        }
        *(float4*)&out[(((o * NP + p) * WID + n) * WID) + m0] = res;
    }
}

extern "C" void kernel_launch(void* const* d_in, const int* in_sizes, int n_in,
                              void* d_out, int out_size) {
    // Bind inputs by size: x=75264, W0=432, W1=756
    const float* x  = (const float*)d_in[0];
    const float* W0 = (const float*)d_in[1];
    const float* W1 = (const float*)d_in[2];
    for (int i = 0; i < n_in; ++i) {
        if (in_sizes[i] == 75264) x  = (const float*)d_in[i];
        else if (in_sizes[i] == 432) W0 = (const float*)d_in[i];
        else if (in_sizes[i] == 756) W1 = (const float*)d_in[i];
    }
    float* out = (float*)d_out;

    fused_sepconv_kernel<<<2 * WID, THREADS>>>(x, W0, W1, out);
}